// round 7
// baseline (speedup 1.0000x reference)
#include <cuda_runtime.h>
#include <cstdint>

// Problem constants
#define NN 100000
#define EE 3200000
#define FIN 512
#define HH 16
#define CC 40

// ---------------- scratch (device globals, referenced DIRECTLY by kernels) --
__device__ float g_h0[NN * HH];
__device__ float g_hlin[NN * HH];
__device__ float g_agg[NN * HH];
__device__ float g_deg[NN];
__device__ float g_dinv[NN];
__device__ int   g_cnt[NN];
__device__ int   g_offs[NN];
__device__ int   g_cur[NN];
__device__ int   g_src[EE];
__device__ float g_nrm[EE];
__device__ int   g_total;

// ---------------- fc1: g_h0 = relu(x @ W_first + b_first) -------------------
#define FC1_TB 256
__global__ void __launch_bounds__(FC1_TB)
k_fc1(const float* __restrict__ x, const float* __restrict__ W,
      const float* __restrict__ b) {
    __shared__ float Wsh[FIN * HH];   // 32 KB
    __shared__ float bsh[HH];
    for (int i = threadIdx.x; i < FIN * HH; i += FC1_TB) Wsh[i] = W[i];
    if (threadIdx.x < HH) bsh[threadIdx.x] = b[threadIdx.x];
    __syncthreads();

    int r = blockIdx.x * FC1_TB + threadIdx.x;
    if (r >= NN) return;
    const float4* xr = (const float4*)(x + (size_t)r * FIN);
    const float4* W4 = (const float4*)Wsh;

    float acc[16];
#pragma unroll
    for (int j = 0; j < 16; j++) acc[j] = bsh[j];

#pragma unroll 4
    for (int kq = 0; kq < FIN / 4; kq++) {
        float4 xv = xr[kq];
        const float4* wr = W4 + kq * 16;
#pragma unroll
        for (int j4 = 0; j4 < 4; j4++) {
            float4 w0 = wr[j4];
            float4 w1 = wr[4 + j4];
            float4 w2 = wr[8 + j4];
            float4 w3 = wr[12 + j4];
            acc[4 * j4 + 0] += xv.x * w0.x + xv.y * w1.x + xv.z * w2.x + xv.w * w3.x;
            acc[4 * j4 + 1] += xv.x * w0.y + xv.y * w1.y + xv.z * w2.y + xv.w * w3.y;
            acc[4 * j4 + 2] += xv.x * w0.z + xv.y * w1.z + xv.z * w2.z + xv.w * w3.z;
            acc[4 * j4 + 3] += xv.x * w0.w + xv.y * w1.w + xv.z * w2.w + xv.w * w3.w;
        }
    }

    float4* dst = (float4*)(g_h0 + (size_t)r * HH);
#pragma unroll
    for (int q = 0; q < 4; q++)
        dst[q] = make_float4(fmaxf(acc[4 * q + 0], 0.0f), fmaxf(acc[4 * q + 1], 0.0f),
                             fmaxf(acc[4 * q + 2], 0.0f), fmaxf(acc[4 * q + 3], 0.0f));
}

// ---------------- init ------------------------------------------------------
__global__ void k_init() {
    int i = blockIdx.x * blockDim.x + threadIdx.x;
    if (i < NN) { g_deg[i] = 1.0f; g_cnt[i] = 0; }
    if (i == 0) g_total = 0;
}

// ---------------- degree + histogram ----------------------------------------
// edge_index is INT32 (JAX default x64-disabled downcasts int64 -> int32).
__global__ void k_deg(const int* __restrict__ ei, const float* __restrict__ ew) {
    int e = blockIdx.x * blockDim.x + threadIdx.x;
    if (e < EE) {
        int c = ei[EE + e];  // row 1 = col = target
        atomicAdd(&g_deg[c], ew[e]);
        atomicAdd(&g_cnt[c], 1);
    }
}

__global__ void k_dinv() {
    int i = blockIdx.x * blockDim.x + threadIdx.x;
    if (i < NN) g_dinv[i] = rsqrtf(g_deg[i]);
}

// ---------------- CSC offsets: warp scan + global cursor --------------------
__global__ void k_offsets() {
    int i = blockIdx.x * blockDim.x + threadIdx.x;
    int lane = threadIdx.x & 31;
    int c = (i < NN) ? g_cnt[i] : 0;
    int v = c;
#pragma unroll
    for (int s = 1; s < 32; s <<= 1) {
        int o = __shfl_up_sync(0xffffffffu, v, s);
        if (lane >= s) v += o;
    }
    int total = __shfl_sync(0xffffffffu, v, 31);
    int base = 0;
    if (lane == 0) base = atomicAdd(&g_total, total);
    base = __shfl_sync(0xffffffffu, base, 0);
    int off = base + v - c;
    if (i < NN) { g_offs[i] = off; g_cur[i] = off; }
}

// ---------------- place edges into CSC slots --------------------------------
__global__ void k_place(const int* __restrict__ ei, const float* __restrict__ ew) {
    int e = blockIdx.x * blockDim.x + threadIdx.x;
    if (e >= EE) return;
    int r = ei[e];        // row 0 = source
    int c = ei[EE + e];   // row 1 = target
    int pos = atomicAdd(&g_cur[c], 1);
    g_src[pos] = r;
    g_nrm[pos] = g_dinv[r] * ew[e] * g_dinv[c];
}

// ---------------- 16x16 linear (optionally pre relu(v + bias)) -------------
// Buffer ids: 0=g_h0, 1=g_hlin, 2=g_agg
__device__ __forceinline__ float* buf(int id) {
    return (id == 0) ? g_h0 : (id == 1) ? g_hlin : g_agg;
}

template <bool PRE, int IN, int OUT>
__global__ void k_lin(const float* __restrict__ W, const float* __restrict__ bpre) {
    __shared__ float Wsh[HH * HH];
    __shared__ float bsh[HH];
    if (threadIdx.x < HH * HH) Wsh[threadIdx.x] = W[threadIdx.x];
    if (PRE && threadIdx.x < HH) bsh[threadIdx.x] = bpre[threadIdx.x];
    __syncthreads();

    int r = blockIdx.x * blockDim.x + threadIdx.x;
    if (r >= NN) return;
    const float4* W4 = (const float4*)Wsh;

    float v[16];
    const float4* ir = (const float4*)(buf(IN) + (size_t)r * HH);
#pragma unroll
    for (int q = 0; q < 4; q++) {
        float4 t = ir[q];
        v[4 * q] = t.x; v[4 * q + 1] = t.y; v[4 * q + 2] = t.z; v[4 * q + 3] = t.w;
    }
    if (PRE) {
#pragma unroll
        for (int j = 0; j < 16; j++) v[j] = fmaxf(v[j] + bsh[j], 0.0f);
    }
    float acc[16];
#pragma unroll
    for (int j = 0; j < 16; j++) acc[j] = 0.0f;
#pragma unroll
    for (int k = 0; k < 16; k++) {
        const float4* wr = W4 + k * 4;
#pragma unroll
        for (int j4 = 0; j4 < 4; j4++) {
            float4 w = wr[j4];
            acc[4 * j4 + 0] += v[k] * w.x;
            acc[4 * j4 + 1] += v[k] * w.y;
            acc[4 * j4 + 2] += v[k] * w.z;
            acc[4 * j4 + 3] += v[k] * w.w;
        }
    }
    float4* dst = (float4*)(buf(OUT) + (size_t)r * HH);
#pragma unroll
    for (int q = 0; q < 4; q++)
        dst[q] = make_float4(acc[4 * q], acc[4 * q + 1], acc[4 * q + 2], acc[4 * q + 3]);
}

// ---------------- CSC gather-aggregate: warp per node, no atomics -----------
template <int IN, int OUT>
__global__ void k_gather() {
    int node = (blockIdx.x * blockDim.x + threadIdx.x) >> 5;
    if (node >= NN) return;
    int lane = threadIdx.x & 31;
    int eg = lane >> 2;   // 0..7
    int f  = lane & 3;    // float4 column 0..3
    int base = g_offs[node];
    int n = g_cnt[node];
    const float4* h = (const float4*)buf(IN);
    float4* outp = (float4*)buf(OUT);

    float ax = 0.0f, ay = 0.0f, az = 0.0f, aw = 0.0f;
    for (int i = eg; i < n; i += 8) {
        int s = g_src[base + i];
        float w = g_nrm[base + i];
        float4 t = h[(size_t)s * 4 + f];
        ax += t.x * w; ay += t.y * w; az += t.z * w; aw += t.w * w;
    }
#pragma unroll
    for (int s = 4; s < 32; s <<= 1) {
        ax += __shfl_xor_sync(0xffffffffu, ax, s);
        ay += __shfl_xor_sync(0xffffffffu, ay, s);
        az += __shfl_xor_sync(0xffffffffu, az, s);
        aw += __shfl_xor_sync(0xffffffffu, aw, s);
    }
    if (lane < 4) {
        float d = g_dinv[node];
        float ws = d * d;
        float4 t = h[(size_t)node * 4 + lane];
        outp[(size_t)node * 4 + lane] =
            make_float4(ax + t.x * ws, ay + t.y * ws, az + t.z * ws, aw + t.w * ws);
    }
}

// ---------------- output layer ----------------------------------------------
__global__ void k_out(const float* __restrict__ b2, const float* __restrict__ Wout,
                      const float* __restrict__ bout, float* __restrict__ out) {
    __shared__ float Wsh[HH * CC];
    __shared__ float bosh[CC];
    __shared__ float b2sh[HH];
    for (int i = threadIdx.x; i < HH * CC; i += blockDim.x) Wsh[i] = Wout[i];
    if (threadIdx.x < CC) bosh[threadIdx.x] = bout[threadIdx.x];
    if (threadIdx.x < HH) b2sh[threadIdx.x] = b2[threadIdx.x];
    __syncthreads();

    int r = blockIdx.x * blockDim.x + threadIdx.x;
    if (r >= NN) return;

    float v[16];
    const float4* ir = (const float4*)(g_agg + (size_t)r * HH);
#pragma unroll
    for (int q = 0; q < 4; q++) {
        float4 t = ir[q];
        v[4 * q] = t.x; v[4 * q + 1] = t.y; v[4 * q + 2] = t.z; v[4 * q + 3] = t.w;
    }
#pragma unroll
    for (int j = 0; j < 16; j++) v[j] = fmaxf(v[j] + b2sh[j], 0.0f);

    float lg[CC];
#pragma unroll
    for (int j = 0; j < CC; j++) lg[j] = bosh[j];
#pragma unroll
    for (int k = 0; k < 16; k++) {
        float vk = v[k];
        const float* wr = &Wsh[k * CC];
#pragma unroll
        for (int j = 0; j < CC; j++) lg[j] += vk * wr[j];
    }
    float m = lg[0];
#pragma unroll
    for (int j = 1; j < CC; j++) m = fmaxf(m, lg[j]);
    float s = 0.0f;
#pragma unroll
    for (int j = 0; j < CC; j++) s += __expf(lg[j] - m);
    float ls = __logf(s) + m;
    float* orow = out + (size_t)r * CC;
#pragma unroll
    for (int j = 0; j < CC; j++) orow[j] = lg[j] - ls;
}

// ---------------- launch: ONLY kernel launches, no other CUDA API -----------
extern "C" void kernel_launch(void* const* d_in, const int* in_sizes, int n_in,
                              void* d_out, int out_size) {
    const float* x       = (const float*)d_in[0];
    const int*   ei      = (const int*)d_in[1];     // int32! (2, E) row-major
    const float* ew      = (const float*)d_in[2];
    const float* W_first = (const float*)d_in[3];
    const float* b_first = (const float*)d_in[4];
    const float* W_c1    = (const float*)d_in[5];
    const float* b_c1    = (const float*)d_in[6];
    const float* W_c2    = (const float*)d_in[7];
    const float* b_c2    = (const float*)d_in[8];
    const float* W_out   = (const float*)d_in[9];
    const float* b_out   = (const float*)d_in[10];
    float* out = (float*)d_out;

    const int TB = 256;
    int gN = (NN + TB - 1) / TB;
    int gE = (EE + TB - 1) / TB;
    int gW = (NN * 32 + TB - 1) / TB;  // warp per node

    // CSC build (shared by both conv layers)
    k_init<<<gN, TB>>>();
    k_deg<<<gE, TB>>>(ei, ew);
    k_dinv<<<gN, TB>>>();
    k_offsets<<<gN, TB>>>();
    k_place<<<gE, TB>>>(ei, ew);

    // fc1 -> g_h0
    k_fc1<<<(NN + FC1_TB - 1) / FC1_TB, FC1_TB>>>(x, W_first, b_first);

    // conv1: g_hlin = g_h0 @ W_c1 ; g_agg = A_norm * g_hlin
    k_lin<false, 0, 1><<<gN, TB>>>(W_c1, b_c1);
    k_gather<1, 2><<<gW, TB>>>();

    // conv2: g_h0 = relu(g_agg + b_c1) @ W_c2 ; g_agg = A_norm * g_h0
    k_lin<true, 2, 0><<<gN, TB>>>(W_c2, b_c1);
    k_gather<0, 2><<<gW, TB>>>();

    // output layer (reads g_agg)
    k_out<<<gN, TB>>>(b_c2, W_out, b_out, out);
}